// round 1
// baseline (speedup 1.0000x reference)
#include <cuda_runtime.h>
#include <math_constants.h>

// Problem constants (fixed by the dataset)
constexpr int B  = 8;
constexpr int T  = 256;
constexpr int U  = 64;
constexpr int U1 = U + 1;    // 65
constexpr int V1 = 1024;
constexpr int ROWS = B * T * U1;   // 133120 softmax rows

// Scratch (device globals — no allocation allowed)
__device__ float g_lp_blank[B * T * U1];   // [B,T,U+1]
__device__ float g_lp_label[B * T * U];    // [B,T,U]
__device__ float g_loglike[B];

// ---------------------------------------------------------------------------
// Kernel 1: per-row logsumexp + gather blank/label log-probs.
// One warp per row of 1024 floats. Each lane holds 8 float4 (32 floats) in
// registers; two register passes (max, sum-exp). HBM-bound streaming kernel.
// ---------------------------------------------------------------------------
__global__ __launch_bounds__(256) void lse_gather_kernel(
    const float* __restrict__ logits, const int* __restrict__ y)
{
    int warp = (blockIdx.x * blockDim.x + threadIdx.x) >> 5;
    int lane = threadIdx.x & 31;
    if (warp >= ROWS) return;

    const float4* row = reinterpret_cast<const float4*>(logits) + (size_t)warp * (V1 / 4);

    float4 v[8];
#pragma unroll
    for (int j = 0; j < 8; j++) v[j] = row[lane + j * 32];

    float m = -CUDART_INF_F;
#pragma unroll
    for (int j = 0; j < 8; j++)
        m = fmaxf(m, fmaxf(fmaxf(v[j].x, v[j].y), fmaxf(v[j].z, v[j].w)));
#pragma unroll
    for (int o = 16; o > 0; o >>= 1) m = fmaxf(m, __shfl_xor_sync(0xFFFFFFFFu, m, o));

    float s = 0.f;
#pragma unroll
    for (int j = 0; j < 8; j++)
        s += __expf(v[j].x - m) + __expf(v[j].y - m) +
             __expf(v[j].z - m) + __expf(v[j].w - m);
#pragma unroll
    for (int o = 16; o > 0; o >>= 1) s += __shfl_xor_sync(0xFFFFFFFFu, s, o);

    float lse = m + __logf(s);

    int b   = warp / (T * U1);
    int rem = warp % (T * U1);
    int t   = rem / U1;
    int u   = rem % U1;

    if (lane == 0) {
        // lane 0 holds element 0 in v[0].x
        g_lp_blank[warp] = v[0].x - lse;
    }
    if (u < U && lane == 1) {
        int lab = y[b * U + u];                           // never 0 (blank)
        float lv = logits[(size_t)warp * V1 + lab];       // L1/L2 hit (just streamed)
        g_lp_label[(b * T + t) * U + u] = lv - lse;
    }
}

// ---------------------------------------------------------------------------
// Kernel 2: forward DP, one block per batch. Anti-diagonal wavefront over the
// [T, U+1] alpha lattice; lp tables staged in dynamic smem; ping-pong
// diagonal buffers; one __syncthreads per diagonal.
//   alpha[t][u] = logaddexp(alpha[t-1][u] + blank[t-1][u],
//                           alpha[t][u-1] + label[t][u-1])
// ---------------------------------------------------------------------------
__global__ __launch_bounds__(128) void dp_kernel(
    const int* __restrict__ logit_lens, const int* __restrict__ y_lens)
{
    extern __shared__ float sm[];
    float* s_blank = sm;             // T*U1 floats
    float* s_label = sm + T * U1;    // T*U  floats
    __shared__ float bufA[U1];
    __shared__ float bufB[U1];

    int b   = blockIdx.x;
    int tid = threadIdx.x;

    const float* gb = g_lp_blank + (size_t)b * T * U1;
    const float* gl = g_lp_label + (size_t)b * T * U;
    for (int i = tid; i < T * U1; i += blockDim.x) s_blank[i] = gb[i];
    for (int i = tid; i < T * U;  i += blockDim.x) s_label[i] = gl[i];

    int t_end = logit_lens[b] - 1;
    int u_end = y_lens[b];

    float* prev = bufA;
    float* cur  = bufB;
    if (tid == 0) prev[0] = 0.f;
    __syncthreads();

    for (int d = 1; d <= (T - 1) + U; d++) {
        int u = tid;
        int t = d - u;
        if (u <= U && t >= 0 && t < T) {
            float val;
            if (u == 0) {
                val = prev[0] + s_blank[(t - 1) * U1];
            } else if (t == 0) {
                val = prev[u - 1] + s_label[u - 1];
            } else {
                float a  = prev[u]     + s_blank[(t - 1) * U1 + u];
                float c  = prev[u - 1] + s_label[t * U + (u - 1)];
                float mx = fmaxf(a, c);
                val = mx + log1pf(__expf(-fabsf(a - c)));
            }
            cur[u] = val;
            if (t == t_end && u == u_end)
                g_loglike[b] = val + s_blank[t * U1 + u];
        }
        __syncthreads();
        float* tmp = prev; prev = cur; cur = tmp;
    }
}

// ---------------------------------------------------------------------------
// Kernel 3: reduce to -mean(log_like)
// ---------------------------------------------------------------------------
__global__ void finish_kernel(float* __restrict__ out)
{
    if (threadIdx.x == 0) {
        float s = 0.f;
#pragma unroll
        for (int b = 0; b < B; b++) s += g_loglike[b];
        out[0] = -s / (float)B;
    }
}

extern "C" void kernel_launch(void* const* d_in, const int* in_sizes, int n_in,
                              void* d_out, int out_size)
{
    const float* logits     = (const float*)d_in[0];   // [B,T,U+1,V1] fp32
    const int*   logit_lens = (const int*)d_in[1];     // [B]
    const int*   y          = (const int*)d_in[2];     // [B,U]
    const int*   y_lens     = (const int*)d_in[3];     // [B]
    float*       out        = (float*)d_out;

    // Phase 1: 133120 rows, 8 warps per 256-thread block
    int blocks = (ROWS + 7) / 8;   // 16640
    lse_gather_kernel<<<blocks, 256>>>(logits, y);

    // Phase 2: DP, one block per batch, 132 KB dynamic smem
    int smem = (T * U1 + T * U) * (int)sizeof(float);  // 132096
    cudaFuncSetAttribute(dp_kernel, cudaFuncAttributeMaxDynamicSharedMemorySize, smem);
    dp_kernel<<<B, 128, smem>>>(logit_lens, y_lens);

    // Phase 3: scalar reduce
    finish_kernel<<<1, 32>>>(out);
}

// round 5
// speedup vs baseline: 1.1022x; 1.1022x over previous
#include <cuda_runtime.h>
#include <math_constants.h>

// Problem constants (fixed by the dataset)
constexpr int B  = 8;
constexpr int T  = 256;
constexpr int U  = 64;
constexpr int U1 = U + 1;    // 65
constexpr int V1 = 1024;
constexpr int ROWS = B * T * U1;   // 133120 softmax rows

// Scratch (device globals — no allocation allowed)
__device__ float g_lp_blank[B * T * U1];   // [B,T,U+1]
__device__ float g_lp_label[B * T * U];    // [B,T,U]
__device__ float g_loglike[B];

// ---------------------------------------------------------------------------
// Kernel 1: per-row logsumexp + gather blank/label log-probs.
// One warp per row of 1024 floats. HBM-bound streaming kernel (85% DRAM).
// ---------------------------------------------------------------------------
__global__ __launch_bounds__(256) void lse_gather_kernel(
    const float* __restrict__ logits, const int* __restrict__ y)
{
    int warp = (blockIdx.x * blockDim.x + threadIdx.x) >> 5;
    int lane = threadIdx.x & 31;
    if (warp >= ROWS) return;

    const float4* row = reinterpret_cast<const float4*>(logits) + (size_t)warp * (V1 / 4);

    float4 v[8];
#pragma unroll
    for (int j = 0; j < 8; j++) v[j] = row[lane + j * 32];

    float m = -CUDART_INF_F;
#pragma unroll
    for (int j = 0; j < 8; j++)
        m = fmaxf(m, fmaxf(fmaxf(v[j].x, v[j].y), fmaxf(v[j].z, v[j].w)));
#pragma unroll
    for (int o = 16; o > 0; o >>= 1) m = fmaxf(m, __shfl_xor_sync(0xFFFFFFFFu, m, o));

    float s = 0.f;
#pragma unroll
    for (int j = 0; j < 8; j++)
        s += __expf(v[j].x - m) + __expf(v[j].y - m) +
             __expf(v[j].z - m) + __expf(v[j].w - m);
#pragma unroll
    for (int o = 16; o > 0; o >>= 1) s += __shfl_xor_sync(0xFFFFFFFFu, s, o);

    float lse = m + __logf(s);

    int b   = warp / (T * U1);
    int rem = warp % (T * U1);
    int t   = rem / U1;
    int u   = rem % U1;

    if (lane == 0) {
        g_lp_blank[warp] = v[0].x - lse;   // lane 0 holds element 0 in v[0].x
    }
    if (u < U && lane == 1) {
        int lab = y[b * U + u];                           // never 0 (blank)
        float lv = logits[(size_t)warp * V1 + lab];       // L1/L2 hit (just streamed)
        g_lp_label[(b * T + t) * U + u] = lv - lse;
    }
}

// ---------------------------------------------------------------------------
// Kernel 2: forward DP, register-resident single-warp wavefront.
// One block per batch; 128 threads stage lp tables to smem (float4); then
// warp 0 runs the anti-diagonal DP entirely in registers:
//   lane l owns u = 2l+1, 2l+2 ; lane 0 additionally owns u = 0.
//   alpha_d[u] = logaddexp(alpha_{d-1}[u] + blank[t-1][u],
//                          alpha_{d-1}[u-1] + label[t][u-1]),  t = d - u
// One __shfl_up per diagonal carries the single cross-lane dependency.
// ---------------------------------------------------------------------------
__global__ __launch_bounds__(128) void dp_kernel(
    const int* __restrict__ logit_lens, const int* __restrict__ y_lens)
{
    extern __shared__ float sm[];
    float* s_blank = sm;             // T*U1 floats (16640)
    float* s_label = sm + T * U1;    // T*U  floats (16384)

    int b   = blockIdx.x;
    int tid = threadIdx.x;

    // Stage lp tables with float4 copies (all counts divisible by 4)
    {
        const float4* gb4 = reinterpret_cast<const float4*>(g_lp_blank + (size_t)b * T * U1);
        const float4* gl4 = reinterpret_cast<const float4*>(g_lp_label + (size_t)b * T * U);
        float4* sb4 = reinterpret_cast<float4*>(s_blank);
        float4* sl4 = reinterpret_cast<float4*>(s_label);
        for (int i = tid; i < (T * U1) / 4; i += 128) sb4[i] = gb4[i];
        for (int i = tid; i < (T * U)  / 4; i += 128) sl4[i] = gl4[i];
    }
    __syncthreads();

    if (tid >= 32) return;

    const int lane = tid;
    const int u_lo = 2 * lane + 1;   // 1..63 (odd)
    const int u_hi = 2 * lane + 2;   // 2..64 (even)

    const int t_end = logit_lens[b] - 1;
    const int u_end = y_lens[b];
    const int d_tgt = t_end + u_end;

    const float NEG_INF = -CUDART_INF_F;
    float a0   = (lane == 0) ? 0.f : NEG_INF;   // alpha[., u=0] (lane 0 only)
    float a_lo = NEG_INF;                       // alpha[., u_lo]
    float a_hi = NEG_INF;                       // alpha[., u_hi]

    for (int d = 1; d <= (T - 1) + U; d++) {
        // Previous-diagonal values
        float p0        = a0;
        float p_lo      = a_lo;
        float p_hi      = a_hi;
        float from_left = __shfl_up_sync(0xFFFFFFFFu, a_hi, 1);  // prev[u_lo-1]
        if (lane == 0) from_left = p0;

        // u = 0 (lane 0): t = d, pure blank chain
        if (lane == 0 && d < T) {
            a0 = p0 + s_blank[(d - 1) * U1];
            if (d == d_tgt && u_end == 0)
                g_loglike[b] = a0 + s_blank[d * U1];
        }

        // u_lo cell: t = d - u_lo
        {
            int t = d - u_lo;
            if (t >= 0 && t < T) {
                float a = (t >= 1) ? p_lo + s_blank[(t - 1) * U1 + u_lo] : NEG_INF;
                float c = from_left + s_label[t * U + (u_lo - 1)];
                float mx = fmaxf(a, c);
                float val = mx + __logf(1.f + __expf(-fabsf(a - c)));
                a_lo = val;
                if (d == d_tgt && u_lo == u_end)
                    g_loglike[b] = val + s_blank[t * U1 + u_lo];
            }
        }

        // u_hi cell: t = d - u_hi ; prev[u_hi-1] = p_lo (own register)
        {
            int t = d - u_hi;
            if (t >= 0 && t < T) {
                float a = (t >= 1) ? p_hi + s_blank[(t - 1) * U1 + u_hi] : NEG_INF;
                float c = p_lo + s_label[t * U + (u_hi - 1)];
                float mx = fmaxf(a, c);
                float val = mx + __logf(1.f + __expf(-fabsf(a - c)));
                a_hi = val;
                if (d == d_tgt && u_hi == u_end)
                    g_loglike[b] = val + s_blank[t * U1 + u_hi];
            }
        }
    }
}

// ---------------------------------------------------------------------------
// Kernel 3: reduce to -mean(log_like)
// ---------------------------------------------------------------------------
__global__ void finish_kernel(float* __restrict__ out)
{
    if (threadIdx.x == 0) {
        float s = 0.f;
#pragma unroll
        for (int b = 0; b < B; b++) s += g_loglike[b];
        out[0] = -s / (float)B;
    }
}

extern "C" void kernel_launch(void* const* d_in, const int* in_sizes, int n_in,
                              void* d_out, int out_size)
{
    const float* logits     = (const float*)d_in[0];   // [B,T,U+1,V1] fp32
    const int*   logit_lens = (const int*)d_in[1];     // [B]
    const int*   y          = (const int*)d_in[2];     // [B,U]
    const int*   y_lens     = (const int*)d_in[3];     // [B]
    float*       out        = (float*)d_out;

    // Phase 1: 133120 rows, 8 warps per 256-thread block (HBM-roofline bound)
    int blocks = (ROWS + 7) / 8;   // 16640
    lse_gather_kernel<<<blocks, 256>>>(logits, y);

    // Phase 2: DP, one block per batch, 132 KB dynamic smem
    int smem = (T * U1 + T * U) * (int)sizeof(float);  // 132096
    cudaFuncSetAttribute(dp_kernel, cudaFuncAttributeMaxDynamicSharedMemorySize, smem);
    dp_kernel<<<B, 128, smem>>>(logit_lens, y_lens);

    // Phase 3: scalar reduce
    finish_kernel<<<1, 32>>>(out);
}

// round 9
// speedup vs baseline: 1.2661x; 1.1487x over previous
#include <cuda_runtime.h>
#include <math_constants.h>

// Problem constants (fixed by the dataset)
constexpr int B  = 8;
constexpr int T  = 256;
constexpr int U  = 64;
constexpr int U1 = U + 1;    // 65
constexpr int V1 = 1024;
constexpr int ROWS = B * T * U1;   // 133120 softmax rows

constexpr float LOG2E = 1.4426950408889634f;
constexpr float LN2   = 0.6931471805599453f;
constexpr float NEG   = -1.0e30f;   // finite "minus infinity" (absorbing in fp32)

// Scratch (device globals — no allocation allowed)
// blankP layout per batch: (T+1) rows of U1; row 0 is the -1e30 pad row,
// row t+1 holds lp2_blank[t][:]  (lp2 = log-prob * log2(e))
__device__ float g_lp2_blankP[B * (T + 1) * U1];
__device__ float g_lp2_label [B * T * U];
__device__ float g_sum;      // zero-init
__device__ int   g_ctr;      // zero-init

__device__ __forceinline__ float ex2f(float x) {
    float r; asm("ex2.approx.ftz.f32 %0, %1;" : "=f"(r) : "f"(x)); return r;
}
__device__ __forceinline__ float lg2f(float x) {
    float r; asm("lg2.approx.ftz.f32 %0, %1;" : "=f"(r) : "f"(x)); return r;
}

// ---------------------------------------------------------------------------
// Kernel 1: per-row logsumexp + gather blank/label log-probs (log2 domain).
// One warp per row of 1024 floats. HBM-roofline bound (86% DRAM) — unchanged
// structure, outputs rescaled by log2(e) and written into the padded table.
// ---------------------------------------------------------------------------
__global__ __launch_bounds__(256) void lse_gather_kernel(
    const float* __restrict__ logits, const int* __restrict__ y)
{
    int warp = (blockIdx.x * blockDim.x + threadIdx.x) >> 5;
    int lane = threadIdx.x & 31;
    if (warp >= ROWS) return;

    const float4* row = reinterpret_cast<const float4*>(logits) + (size_t)warp * (V1 / 4);

    float4 v[8];
#pragma unroll
    for (int j = 0; j < 8; j++) v[j] = row[lane + j * 32];

    float m = -CUDART_INF_F;
#pragma unroll
    for (int j = 0; j < 8; j++)
        m = fmaxf(m, fmaxf(fmaxf(v[j].x, v[j].y), fmaxf(v[j].z, v[j].w)));
#pragma unroll
    for (int o = 16; o > 0; o >>= 1) m = fmaxf(m, __shfl_xor_sync(0xFFFFFFFFu, m, o));

    float s = 0.f;
#pragma unroll
    for (int j = 0; j < 8; j++)
        s += __expf(v[j].x - m) + __expf(v[j].y - m) +
             __expf(v[j].z - m) + __expf(v[j].w - m);
#pragma unroll
    for (int o = 16; o > 0; o >>= 1) s += __shfl_xor_sync(0xFFFFFFFFu, s, o);

    float lse = m + __logf(s);

    int b   = warp / (T * U1);
    int rem = warp % (T * U1);
    int t   = rem / U1;
    int u   = rem % U1;

    float* bp = g_lp2_blankP + (size_t)b * (T + 1) * U1;

    if (lane == 0) {
        bp[(t + 1) * U1 + u] = (v[0].x - lse) * LOG2E;   // lane 0 holds element 0
    }
    if (t == 0 && lane == 2) {
        bp[u] = NEG;                                     // pad row
    }
    if (u < U && lane == 1) {
        int lab = y[b * U + u];                          // never 0 (blank)
        float lv = logits[(size_t)warp * V1 + lab];      // L1/L2 hit (just streamed)
        g_lp2_label[(size_t)(b * T + t) * U + u] = (lv - lse) * LOG2E;
    }
}

// ---------------------------------------------------------------------------
// Kernel 2: forward DP — branchless register wavefront, one warp per batch.
// lane l owns u = 2l+1, 2l+2 ; all lanes redundantly carry the u=0 chain.
//   alpha[t][u] = logaddexp2(alpha[t-1][u] + blankP[t][u],
//                            alpha[t][u-1] + label[t][u-1]),  t = d - u
// Edge cases are handled by index clamping into the padded blank table and
// -1e30 absorption; no branches inside the loop. Loads come from L2 and are
// software-pipelined by unrolling (indices depend only on d).
// Last block reduces and writes the final loss (threadfence + atomic counter).
// ---------------------------------------------------------------------------
__global__ __launch_bounds__(32) void dp_kernel(
    const int* __restrict__ logit_lens, const int* __restrict__ y_lens,
    float* __restrict__ out)
{
    const int b    = blockIdx.x;
    const int lane = threadIdx.x;

    const float* Bp = g_lp2_blankP + (size_t)b * (T + 1) * U1;
    const float* Lb = g_lp2_label  + (size_t)b * T * U;

    const int u_lo = 2 * lane + 1;   // 1..63
    const int u_hi = 2 * lane + 2;   // 2..64

    const int t_end = logit_lens[b] - 1;
    const int u_end = y_lens[b];
    const int d_tgt = t_end + u_end;          // in [1, 319]

    const bool own0 = (lane == 0) && (u_end == 0);
    const bool ownL = (u_end == u_lo);
    const bool ownH = (u_end == u_hi);

    float a0   = (lane == 0) ? 0.f : NEG;
    float a_lo = NEG;
    float a_hi = NEG;
    float res  = NEG;

#pragma unroll 4
    for (int d = 1; d <= (T - 1) + U; d++) {
        // previous-diagonal values
        float p0   = a0;
        float p_lo = a_lo;
        float p_hi = a_hi;
        float fl   = __shfl_up_sync(0xFFFFFFFFu, a_hi, 1);   // prev[u_lo-1]
        fl = (lane == 0) ? p0 : fl;

        // clamped table indices (depend only on d -> pipelined ahead)
        int tl = d - u_lo;
        int th = d - u_hi;
        int rAl = min(max(tl, 0), T);
        int rAh = min(max(th, 0), T);
        int rCl = min(max(tl, 0), T - 1);
        int rCh = min(max(th, 0), T - 1);

        float bl_lo = __ldg(&Bp[rAl * U1 + u_lo]);
        float bl_hi = __ldg(&Bp[rAh * U1 + u_hi]);
        float lb_lo = __ldg(&Lb[rCl * U + (u_lo - 1)]);
        float lb_hi = __ldg(&Lb[rCh * U + (u_hi - 1)]);
        float b0    = __ldg(&Bp[min(d, T) * U1]);            // blank[d-1][0]

        // u = 0 chain (meaningful on lane 0 only; harmless elsewhere)
        a0 = p0 + b0;

        // u_lo cell
        float aL = p_lo + bl_lo;
        float cL = fl   + lb_lo;
        float mL = fmaxf(aL, cL);
        a_lo = mL + lg2f(1.f + ex2f(-fabsf(aL - cL)));

        // u_hi cell (prev[u_hi-1] = p_lo, own register)
        float aH = p_hi + bl_hi;
        float cH = p_lo + lb_hi;
        float mH = fmaxf(aH, cH);
        a_hi = mH + lg2f(1.f + ex2f(-fabsf(aH - cH)));

        // harvest (predicated selects, off the critical chain)
        if (d == d_tgt) {
            res = ownL ? a_lo : res;
            res = ownH ? a_hi : res;
            res = own0 ? a0   : res;
        }
    }

    // reduce the single matched value across the warp
    float cand = (own0 | ownL | ownH) ? res : -3.0e38f;
#pragma unroll
    for (int o = 16; o > 0; o >>= 1)
        cand = fmaxf(cand, __shfl_xor_sync(0xFFFFFFFFu, cand, o));

    if (lane == 0) {
        float bfin = __ldg(&Bp[(t_end + 1) * U1 + u_end]);   // lp2_blank[t_end][u_end]
        float ll   = (cand + bfin) * LN2;                    // back to natural log

        atomicAdd(&g_sum, ll);
        __threadfence();
        int old = atomicAdd(&g_ctr, 1);
        if (old == B - 1) {
            __threadfence();
            float total = atomicAdd(&g_sum, 0.f);            // atomic read of final sum
            out[0] = -total / (float)B;
            g_sum = 0.f;                                     // reset for next replay
            g_ctr = 0;
        }
    }
}

extern "C" void kernel_launch(void* const* d_in, const int* in_sizes, int n_in,
                              void* d_out, int out_size)
{
    const float* logits     = (const float*)d_in[0];   // [B,T,U+1,V1] fp32
    const int*   logit_lens = (const int*)d_in[1];     // [B]
    const int*   y          = (const int*)d_in[2];     // [B,U]
    const int*   y_lens     = (const int*)d_in[3];     // [B]
    float*       out        = (float*)d_out;

    // Phase 1: 133120 rows, 8 warps per 256-thread block (HBM-roofline bound)
    int blocks = (ROWS + 7) / 8;   // 16640
    lse_gather_kernel<<<blocks, 256>>>(logits, y);

    // Phase 2: branchless DP + fused final reduction, one warp per batch
    dp_kernel<<<B, 32>>>(logit_lens, y_lens, out);
}

// round 11
// speedup vs baseline: 1.6594x; 1.3106x over previous
#include <cuda_runtime.h>
#include <math_constants.h>

// Problem constants (fixed by the dataset)
constexpr int B  = 8;
constexpr int T  = 256;
constexpr int U  = 64;
constexpr int U1 = U + 1;    // 65
constexpr int V1 = 1024;
constexpr int ROWS = B * T * U1;   // 133120 softmax rows

constexpr int SB = 66;                       // padded blank row stride (bank-conflict fix)
constexpr int BLANK_N = ((T + 1) * SB + 3) & ~3;   // 16964 floats per batch (float4-able)

constexpr float LOG2E = 1.4426950408889634f;
constexpr float LN2   = 0.6931471805599453f;
constexpr float NEG   = -1.0e30f;   // finite "minus infinity" (absorbing in fp32)

// Scratch (device globals — no allocation allowed)
// blankP layout per batch: (T+1) rows of stride SB=66; row 0 is the -1e30 pad
// row, row t+1 holds lp2_blank[t][:]  (lp2 = log-prob * log2(e))
__device__ float g_lp2_blankP[B * BLANK_N];
__device__ float g_lp2_label [B * T * U];
__device__ float g_sum;      // zero-init
__device__ int   g_ctr;      // zero-init

__device__ __forceinline__ float ex2f(float x) {
    float r; asm("ex2.approx.ftz.f32 %0, %1;" : "=f"(r) : "f"(x)); return r;
}
__device__ __forceinline__ float lg2f(float x) {
    float r; asm("lg2.approx.ftz.f32 %0, %1;" : "=f"(r) : "f"(x)); return r;
}

// ---------------------------------------------------------------------------
// Kernel 1: per-row logsumexp + gather blank/label log-probs (log2 domain).
// One warp per row of 1024 floats. HBM-roofline bound (86% DRAM).
// Blank output goes into the padded stride-66 table.
// ---------------------------------------------------------------------------
__global__ __launch_bounds__(256) void lse_gather_kernel(
    const float* __restrict__ logits, const int* __restrict__ y)
{
    int warp = (blockIdx.x * blockDim.x + threadIdx.x) >> 5;
    int lane = threadIdx.x & 31;
    if (warp >= ROWS) return;

    const float4* row = reinterpret_cast<const float4*>(logits) + (size_t)warp * (V1 / 4);

    float4 v[8];
#pragma unroll
    for (int j = 0; j < 8; j++) v[j] = row[lane + j * 32];

    float m = -CUDART_INF_F;
#pragma unroll
    for (int j = 0; j < 8; j++)
        m = fmaxf(m, fmaxf(fmaxf(v[j].x, v[j].y), fmaxf(v[j].z, v[j].w)));
#pragma unroll
    for (int o = 16; o > 0; o >>= 1) m = fmaxf(m, __shfl_xor_sync(0xFFFFFFFFu, m, o));

    float s = 0.f;
#pragma unroll
    for (int j = 0; j < 8; j++)
        s += __expf(v[j].x - m) + __expf(v[j].y - m) +
             __expf(v[j].z - m) + __expf(v[j].w - m);
#pragma unroll
    for (int o = 16; o > 0; o >>= 1) s += __shfl_xor_sync(0xFFFFFFFFu, s, o);

    float lse = m + __logf(s);

    int b   = warp / (T * U1);
    int rem = warp % (T * U1);
    int t   = rem / U1;
    int u   = rem % U1;

    float* bp = g_lp2_blankP + (size_t)b * BLANK_N;

    if (lane == 0) {
        bp[(t + 1) * SB + u] = (v[0].x - lse) * LOG2E;   // lane 0 holds element 0
    }
    if (t == 0 && lane == 2) {
        bp[u] = NEG;                                     // pad row (t = -1)
    }
    if (u < U && lane == 1) {
        int lab = y[b * U + u];                          // never 0 (blank)
        float lv = logits[(size_t)warp * V1 + lab];      // L1/L2 hit (just streamed)
        g_lp2_label[(size_t)(b * T + t) * U + u] = (lv - lse) * LOG2E;
    }
}

// ---------------------------------------------------------------------------
// Kernel 2: forward DP — branchless register wavefront over smem tables.
// 256 threads stage both tables to shared memory (flat float4), one
// __syncthreads, then warp 0 runs the whole DP:
//   lane l owns u = 2l+1, 2l+2 ; all lanes redundantly carry the u=0 chain.
//   alpha[t][u] = logaddexp2(alpha[t-1][u] + blankP[t][u],
//                            alpha[t][u-1] + label[t][u-1]),  t = d - u
// Edges via index clamps into the padded table + -1e30 absorption; zero
// branches in the loop. LDS (29 cyc, 2-way conflicts by stride choice) hides
// under the ~100-cyc logaddexp chain. Last block fuses the final reduction.
// ---------------------------------------------------------------------------
__global__ __launch_bounds__(256) void dp_kernel(
    const int* __restrict__ logit_lens, const int* __restrict__ y_lens,
    float* __restrict__ out)
{
    extern __shared__ float sm[];
    float* s_blank = sm;               // BLANK_N floats, row stride SB=66
    float* s_label = sm + BLANK_N;     // T*U floats, row stride 64

    const int b   = blockIdx.x;
    const int tid = threadIdx.x;

    // Stage tables (flat float4 copies)
    {
        const float4* gb4 = reinterpret_cast<const float4*>(g_lp2_blankP + (size_t)b * BLANK_N);
        const float4* gl4 = reinterpret_cast<const float4*>(g_lp2_label  + (size_t)b * T * U);
        float4* sb4 = reinterpret_cast<float4*>(s_blank);
        float4* sl4 = reinterpret_cast<float4*>(s_label);
        for (int i = tid; i < BLANK_N / 4; i += 256) sb4[i] = gb4[i];
        for (int i = tid; i < (T * U) / 4; i += 256) sl4[i] = gl4[i];
    }
    __syncthreads();
    if (tid >= 32) return;

    const int lane = tid;
    const int u_lo = 2 * lane + 1;   // 1..63
    const int u_hi = 2 * lane + 2;   // 2..64

    const int t_end = logit_lens[b] - 1;
    const int u_end = y_lens[b];
    const int d_tgt = t_end + u_end;          // in [1, 319]

    const bool own0 = (lane == 0) && (u_end == 0);
    const bool ownL = (u_end == u_lo);
    const bool ownH = (u_end == u_hi);

    float a0   = (lane == 0) ? 0.f : NEG;
    float a_lo = NEG;
    float a_hi = NEG;
    float res  = NEG;

#pragma unroll 4
    for (int d = 1; d <= (T - 1) + U; d++) {
        // previous-diagonal values
        float p0   = a0;
        float p_lo = a_lo;
        float p_hi = a_hi;
        float fl   = __shfl_up_sync(0xFFFFFFFFu, a_hi, 1);   // prev[u_lo-1]
        fl = (lane == 0) ? p0 : fl;

        // clamped table indices (depend only on d — off the alpha chain)
        int tl = d - u_lo;
        int th = d - u_hi;
        int rAl = min(max(tl, 0), T);
        int rAh = min(max(th, 0), T);
        int rCl = min(max(tl, 0), T - 1);
        int rCh = min(max(th, 0), T - 1);

        float bl_lo = s_blank[rAl * SB + u_lo];
        float bl_hi = s_blank[rAh * SB + u_hi];
        float lb_lo = s_label[rCl * U + (u_lo - 1)];
        float lb_hi = s_label[rCh * U + (u_hi - 1)];
        float b0    = s_blank[min(d, T) * SB];               // blank[d-1][0] (broadcast)

        // u = 0 chain (meaningful on lane 0 only; harmless elsewhere)
        a0 = p0 + b0;

        // u_lo cell
        float aL = p_lo + bl_lo;
        float cL = fl   + lb_lo;
        float mL = fmaxf(aL, cL);
        a_lo = mL + lg2f(1.f + ex2f(-fabsf(aL - cL)));

        // u_hi cell (prev[u_hi-1] = p_lo, own register)
        float aH = p_hi + bl_hi;
        float cH = p_lo + lb_hi;
        float mH = fmaxf(aH, cH);
        a_hi = mH + lg2f(1.f + ex2f(-fabsf(aH - cH)));

        // harvest (predicated selects, off the critical chain)
        if (d == d_tgt) {
            res = ownL ? a_lo : res;
            res = ownH ? a_hi : res;
            res = own0 ? a0   : res;
        }
    }

    // reduce the single matched value across the warp
    float cand = (own0 | ownL | ownH) ? res : -3.0e38f;
#pragma unroll
    for (int o = 16; o > 0; o >>= 1)
        cand = fmaxf(cand, __shfl_xor_sync(0xFFFFFFFFu, cand, o));

    if (lane == 0) {
        float bfin = s_blank[(t_end + 1) * SB + u_end];      // lp2_blank[t_end][u_end]
        float ll   = (cand + bfin) * LN2;                    // back to natural log

        atomicAdd(&g_sum, ll);
        __threadfence();
        int old = atomicAdd(&g_ctr, 1);
        if (old == B - 1) {
            __threadfence();
            float total = atomicAdd(&g_sum, 0.f);            // atomic read of final sum
            out[0] = -total / (float)B;
            g_sum = 0.f;                                     // reset for next replay
            g_ctr = 0;
        }
    }
}

extern "C" void kernel_launch(void* const* d_in, const int* in_sizes, int n_in,
                              void* d_out, int out_size)
{
    const float* logits     = (const float*)d_in[0];   // [B,T,U+1,V1] fp32
    const int*   logit_lens = (const int*)d_in[1];     // [B]
    const int*   y          = (const int*)d_in[2];     // [B,U]
    const int*   y_lens     = (const int*)d_in[3];     // [B]
    float*       out        = (float*)d_out;

    // Phase 1: 133120 rows, 8 warps per 256-thread block (HBM-roofline bound)
    int blocks = (ROWS + 7) / 8;   // 16640
    lse_gather_kernel<<<blocks, 256>>>(logits, y);

    // Phase 2: branchless DP over smem tables + fused final reduction
    int smem = (BLANK_N + T * U) * (int)sizeof(float);  // 133392 B
    cudaFuncSetAttribute(dp_kernel, cudaFuncAttributeMaxDynamicSharedMemorySize, smem);
    dp_kernel<<<B, 256, smem>>>(logit_lens, y_lens, out);
}

// round 14
// speedup vs baseline: 1.7217x; 1.0376x over previous
#include <cuda_runtime.h>
#include <math_constants.h>

// Problem constants (fixed by the dataset)
constexpr int B  = 8;
constexpr int T  = 256;
constexpr int U  = 64;
constexpr int U1 = U + 1;    // 65
constexpr int V1 = 1024;
constexpr int ROWS = B * T * U1;   // 133120 softmax rows

constexpr int SB = 66;                       // padded blank row stride (bank-conflict fix)
constexpr int BLANK_N = ((T + 1) * SB + 3) & ~3;   // floats per batch (float4-able)

constexpr float LOG2E = 1.4426950408889634f;
constexpr float LN2   = 0.6931471805599453f;
constexpr float NEG   = -1.0e30f;   // finite "minus infinity" (absorbing in fp32)

// Scratch (device globals — no allocation allowed)
// blankP layout per batch: (T+1) rows of stride SB=66; row 0 is the -1e30 pad
// row, row t+1 holds lp2_blank[t][:]  (lp2 = log-prob * log2(e))
__device__ float g_lp2_blankP[B * BLANK_N];
__device__ float g_lp2_label [B * T * U];
__device__ float g_sum;      // zero-init
__device__ int   g_ctr;      // zero-init

__device__ __forceinline__ float ex2f(float x) {
    float r; asm("ex2.approx.ftz.f32 %0, %1;" : "=f"(r) : "f"(x)); return r;
}
__device__ __forceinline__ float lg2f(float x) {
    float r; asm("lg2.approx.ftz.f32 %0, %1;" : "=f"(r) : "f"(x)); return r;
}

// ---------------------------------------------------------------------------
// Kernel 1: per-row logsumexp + gather blank/label log-probs (log2 domain).
// One warp per row of 1024 floats. HBM-roofline bound (86% DRAM).
// Blank output goes into the padded stride-66 table.
// ---------------------------------------------------------------------------
__global__ __launch_bounds__(256) void lse_gather_kernel(
    const float* __restrict__ logits, const int* __restrict__ y)
{
    int warp = (blockIdx.x * blockDim.x + threadIdx.x) >> 5;
    int lane = threadIdx.x & 31;
    if (warp >= ROWS) return;

    const float4* row = reinterpret_cast<const float4*>(logits) + (size_t)warp * (V1 / 4);

    float4 v[8];
#pragma unroll
    for (int j = 0; j < 8; j++) v[j] = row[lane + j * 32];

    float m = -CUDART_INF_F;
#pragma unroll
    for (int j = 0; j < 8; j++)
        m = fmaxf(m, fmaxf(fmaxf(v[j].x, v[j].y), fmaxf(v[j].z, v[j].w)));
#pragma unroll
    for (int o = 16; o > 0; o >>= 1) m = fmaxf(m, __shfl_xor_sync(0xFFFFFFFFu, m, o));

    float s = 0.f;
#pragma unroll
    for (int j = 0; j < 8; j++)
        s += __expf(v[j].x - m) + __expf(v[j].y - m) +
             __expf(v[j].z - m) + __expf(v[j].w - m);
#pragma unroll
    for (int o = 16; o > 0; o >>= 1) s += __shfl_xor_sync(0xFFFFFFFFu, s, o);

    float lse = m + __logf(s);

    int b   = warp / (T * U1);
    int rem = warp % (T * U1);
    int t   = rem / U1;
    int u   = rem % U1;

    float* bp = g_lp2_blankP + (size_t)b * BLANK_N;

    if (lane == 0) {
        bp[(t + 1) * SB + u] = (v[0].x - lse) * LOG2E;   // lane 0 holds element 0
    }
    if (t == 0 && lane == 2) {
        bp[u] = NEG;                                     // pad row (t = -1)
    }
    if (u < U && lane == 1) {
        int lab = y[b * U + u];                          // never 0 (blank)
        float lv = logits[(size_t)warp * V1 + lab];      // L1/L2 hit (just streamed)
        g_lp2_label[(size_t)(b * T + t) * U + u] = (lv - lse) * LOG2E;
    }
}

// ---------------------------------------------------------------------------
// Kernel 2: forward DP — branchless register wavefront over smem tables.
// 256 threads stage both tables to shared memory (flat float4), one
// __syncthreads, then warp 0 runs the whole DP.
//   lane l owns u = 2l+1, 2l+2 ; all lanes redundantly carry the u=0 chain.
//   alpha[t][u] = logaddexp2(alpha[t-1][u] + blankP[t][u],
//                            alpha[t][u-1] + label[t][u-1]),  t = d - u
// R12: loop runs only to d_tgt (warp-uniform), table loads are manually
// software-pipelined one diagonal ahead (hides LDS latency under the
// logaddexp chain), and the harvest is hoisted out of the loop (state at
// loop exit IS the target diagonal).
// ---------------------------------------------------------------------------
__global__ __launch_bounds__(256) void dp_kernel(
    const int* __restrict__ logit_lens, const int* __restrict__ y_lens,
    float* __restrict__ out)
{
    extern __shared__ float sm[];
    float* s_blank = sm;               // BLANK_N floats, row stride SB=66
    float* s_label = sm + BLANK_N;     // T*U floats, row stride 64

    const int b   = blockIdx.x;
    const int tid = threadIdx.x;

    // Stage tables (flat float4 copies)
    {
        const float4* gb4 = reinterpret_cast<const float4*>(g_lp2_blankP + (size_t)b * BLANK_N);
        const float4* gl4 = reinterpret_cast<const float4*>(g_lp2_label  + (size_t)b * T * U);
        float4* sb4 = reinterpret_cast<float4*>(s_blank);
        float4* sl4 = reinterpret_cast<float4*>(s_label);
        for (int i = tid; i < BLANK_N / 4; i += 256) sb4[i] = gb4[i];
        for (int i = tid; i < (T * U) / 4; i += 256) sl4[i] = gl4[i];
    }
    __syncthreads();
    if (tid >= 32) return;

    const int lane = tid;
    const int u_lo = 2 * lane + 1;   // 1..63
    const int u_hi = 2 * lane + 2;   // 2..64

    const int t_end = logit_lens[b] - 1;
    const int u_end = y_lens[b];
    const int d_tgt = t_end + u_end;          // in [1, 319]; loop ends exactly here

    float a0   = (lane == 0) ? 0.f : NEG;
    float a_lo = NEG;
    float a_hi = NEG;

    // ---- software-pipelined table values (prefetched one diagonal ahead) ----
    float bl_lo, bl_hi, lb_lo, lb_hi, b0;
    {
        const int d = 1;
        int tl = d - u_lo, th = d - u_hi;
        bl_lo = s_blank[min(max(tl, 0), T) * SB + u_lo];
        bl_hi = s_blank[min(max(th, 0), T) * SB + u_hi];
        lb_lo = s_label[min(max(tl, 0), T - 1) * U + (u_lo - 1)];
        lb_hi = s_label[min(max(th, 0), T - 1) * U + (u_hi - 1)];
        b0    = s_blank[min(d, T) * SB];
    }

#pragma unroll 2
    for (int d = 1; d <= d_tgt; d++) {
        // consume current diagonal's prefetched values
        const float cbl_lo = bl_lo, cbl_hi = bl_hi;
        const float clb_lo = lb_lo, clb_hi = lb_hi;
        const float cb0    = b0;

        // prefetch diagonal d+1 (indices depend only on d — off the chain;
        // clamps keep everything in-bounds past the end)
        {
            const int dn = d + 1;
            int tl = dn - u_lo, th = dn - u_hi;
            bl_lo = s_blank[min(max(tl, 0), T) * SB + u_lo];
            bl_hi = s_blank[min(max(th, 0), T) * SB + u_hi];
            lb_lo = s_label[min(max(tl, 0), T - 1) * U + (u_lo - 1)];
            lb_hi = s_label[min(max(th, 0), T - 1) * U + (u_hi - 1)];
            b0    = s_blank[min(dn, T) * SB];
        }

        // previous-diagonal values
        float p0   = a0;
        float p_lo = a_lo;
        float p_hi = a_hi;
        float fl   = __shfl_up_sync(0xFFFFFFFFu, a_hi, 1);   // prev[u_lo-1]
        fl = (lane == 0) ? p0 : fl;

        // u = 0 chain (meaningful on lane 0 only; harmless elsewhere)
        a0 = p0 + cb0;

        // u_lo cell
        float aL = p_lo + cbl_lo;
        float cL = fl   + clb_lo;
        float mL = fmaxf(aL, cL);
        a_lo = mL + lg2f(1.f + ex2f(-fabsf(aL - cL)));

        // u_hi cell (prev[u_hi-1] = p_lo, own register)
        float aH = p_hi + cbl_hi;
        float cH = p_lo + clb_hi;
        float mH = fmaxf(aH, cH);
        a_hi = mH + lg2f(1.f + ex2f(-fabsf(aH - cH)));
    }

    // Harvest: loop exited with state at diagonal d_tgt.
    float res = NEG;
    res = (u_end == u_lo)              ? a_lo : res;
    res = (u_end == u_hi)              ? a_hi : res;
    res = (lane == 0 && u_end == 0)    ? a0   : res;

    // reduce the single matched value across the warp
    float cand = fmaxf(res, -3.0e38f);
#pragma unroll
    for (int o = 16; o > 0; o >>= 1)
        cand = fmaxf(cand, __shfl_xor_sync(0xFFFFFFFFu, cand, o));

    if (lane == 0) {
        float bfin = s_blank[(t_end + 1) * SB + u_end];      // lp2_blank[t_end][u_end]
        float ll   = (cand + bfin) * LN2;                    // back to natural log

        atomicAdd(&g_sum, ll);
        __threadfence();
        int old = atomicAdd(&g_ctr, 1);
        if (old == B - 1) {
            __threadfence();
            float total = atomicAdd(&g_sum, 0.f);            // atomic read of final sum
            out[0] = -total / (float)B;
            g_sum = 0.f;                                     // reset for next replay
            g_ctr = 0;
        }
    }
}

extern "C" void kernel_launch(void* const* d_in, const int* in_sizes, int n_in,
                              void* d_out, int out_size)
{
    const float* logits     = (const float*)d_in[0];   // [B,T,U+1,V1] fp32
    const int*   logit_lens = (const int*)d_in[1];     // [B]
    const int*   y          = (const int*)d_in[2];     // [B,U]
    const int*   y_lens     = (const int*)d_in[3];     // [B]
    float*       out        = (float*)d_out;

    // Phase 1: 133120 rows, 8 warps per 256-thread block (HBM-roofline bound)
    int blocks = (ROWS + 7) / 8;   // 16640
    lse_gather_kernel<<<blocks, 256>>>(logits, y);

    // Phase 2: branchless DP over smem tables + fused final reduction
    int smem = (BLANK_N + T * U) * (int)sizeof(float);  // 133392 B
    cudaFuncSetAttribute(dp_kernel, cudaFuncAttributeMaxDynamicSharedMemorySize, smem);
    dp_kernel<<<B, 256, smem>>>(logit_lens, y_lens, out);
}